// round 1
// baseline (speedup 1.0000x reference)
#include <cuda_runtime.h>
#include <cstdint>
#include <cstddef>

#define SEQ   2048
#define BATCH 128
#define HID   256
#define KP    128          // f32-pairs per W row (256 cols / 2)
#define KREG  88           // pairs held in registers per thread (176 cols)
#define KSM   (KP - KREG)  // 40 pairs (80 cols) served from shared memory

typedef unsigned long long u64;

// W_eff packed as f32x2 pairs: pair k of row i at g_Wp[k*HID + i]
__device__ u64 g_Wp[KP * HID];

__device__ __forceinline__ u64 ffma2(u64 a, u64 b, u64 c) {
    u64 d;
    asm("fma.rn.f32x2 %0, %1, %2, %3;" : "=l"(d) : "l"(a), "l"(b), "l"(c));
    return d;
}
__device__ __forceinline__ float lo32(u64 v) { return __uint_as_float((unsigned)(v & 0xffffffffu)); }
__device__ __forceinline__ float hi32(u64 v) { return __uint_as_float((unsigned)(v >> 32)); }

// ---------------------------------------------------------------------------
// Prep: W_eff = W_hh + context * W_hh_bias, packed into pair-major layout.
// context dtype is sniffed (int32/int64 low word, or float32 bit pattern).
// ---------------------------------------------------------------------------
__global__ void prep_kernel(const float* __restrict__ Whh,
                            const float* __restrict__ Whb,
                            const void*  __restrict__ ctxp) {
    int idx = blockIdx.x * blockDim.x + threadIdx.x;   // 32768 threads
    int k = idx >> 8;
    int i = idx & 255;
    int iv = *(const int*)ctxp;
    float ctx = (iv > -1000000 && iv < 1000000) ? (float)iv : *(const float*)ctxp;
    float w0 = fmaf(ctx, Whb[i * HID + 2 * k],     Whh[i * HID + 2 * k]);
    float w1 = fmaf(ctx, Whb[i * HID + 2 * k + 1], Whh[i * HID + 2 * k + 1]);
    g_Wp[k * HID + i] = (u64)__float_as_uint(w0) | ((u64)__float_as_uint(w1) << 32);
}

// ---------------------------------------------------------------------------
// Persistent recurrence: one CTA per batch element, 256 threads (thread i owns
// hidden unit i). 176 W columns in registers, 80 from smem. One barrier/step.
// ---------------------------------------------------------------------------
__global__ void __launch_bounds__(HID, 1) rnn_kernel(
    const float* __restrict__ x,     const float* __restrict__ h0,
    const float* __restrict__ noise, const float* __restrict__ W_ih,
    const float* __restrict__ b_h,   const float* __restrict__ Wout,
    const float* __restrict__ bout,  float* __restrict__ y_out,
    float* __restrict__ h_out)
{
    extern __shared__ u64 sm[];
    u64*   Wsm  = sm;                              // KSM*HID u64 = 80 KB
    float* hb   = (float*)(sm + KSM * HID);        // 2 * HID (double-buffered h)
    float* part = hb + 2 * HID;                    // 2 * 8 warp partials (parity)

    const int b = blockIdx.x;
    const int i = threadIdx.x;
    const int lane = i & 31, wid = i >> 5;

    // Stage the smem-resident W pairs (coalesced u64 loads, once).
    for (int idx = i; idx < KSM * HID; idx += HID)
        Wsm[idx] = g_Wp[KREG * HID + idx];

    // Register-resident W pairs (coalesced across threads per k).
    u64 Wreg[KREG];
#pragma unroll
    for (int k = 0; k < KREG; k++) Wreg[k] = g_Wp[k * HID + i];

    const float win = W_ih[i];
    const float bh  = b_h[i];
    const float wy  = Wout[i];     // W[0, i]  (only o=0 is emitted)
    const float by  = bout[0];

    hb[i] = h0[b * HID + i];
    __syncthreads();

    const float* np = noise + (size_t)b * HID + i;
    float*       op = h_out + (size_t)b * SEQ * HID + i;
    const float* xp = x + b;

    for (int t = 0; t < SEQ; t++) {
        const int cur = t & 1;

        // Prefetch streamed inputs early; consumed ~600+ cycles later.
        const float nz = __ldg(np + (size_t)t * (BATCH * HID));
        const float xv = __ldg(xp + t * BATCH);

        const ulonglong2* h4 = (const ulonglong2*)(hb + cur * HID);
        u64 a0 = 0, a1 = 0, a2 = 0, a3 = 0;

        // Register part: j in [0, 176)
#pragma unroll
        for (int kk = 0; kk < KREG / 2; kk++) {
            ulonglong2 hh = h4[kk];                  // LDS.128 broadcast
            a0 = ffma2(Wreg[2 * kk],     hh.x, a0);
            a1 = ffma2(Wreg[2 * kk + 1], hh.y, a1);
        }
        // Smem part: j in [176, 256)  (conflict-free LDS.64: lanes contiguous)
#pragma unroll
        for (int gg = 0; gg < KSM / 2; gg++) {
            ulonglong2 hh = h4[KREG / 2 + gg];
            a2 = ffma2(Wsm[(2 * gg) * HID + i],     hh.x, a2);
            a3 = ffma2(Wsm[(2 * gg + 1) * HID + i], hh.y, a3);
        }

        float s = ((lo32(a0) + hi32(a0)) + (lo32(a1) + hi32(a1)))
                + ((lo32(a2) + hi32(a2)) + (lo32(a3) + hi32(a3)));
        float pre = fmaf(xv, win, s) + bh;
        float hn  = tanhf(pre) + nz;

        hb[(cur ^ 1) * HID + i] = hn;         // next-step h (other parity slot)
        op[(size_t)t * HID] = hn;             // out[b, t, i] (coalesced)

        // y[b, t] = sigmoid(<h_new, W[0,:]> + b[0]) : warp shfl + smem partials
        float c = hn * wy;
#pragma unroll
        for (int o = 16; o > 0; o >>= 1) c += __shfl_down_sync(0xffffffffu, c, o);
        if (lane == 0) part[cur * 8 + wid] = c;

        __syncthreads();

        if (i == 0) {
            float sy = 0.0f;
#pragma unroll
            for (int w = 0; w < 8; w++) sy += part[cur * 8 + w];
            y_out[(size_t)b * SEQ + t] = 1.0f / (1.0f + expf(-(sy + by)));
        }
    }
}

// ---------------------------------------------------------------------------
// Launch: inputs in metadata order
//   x, h0, noise, W_ih, W_hh, W_hh_bias, b_h, W, b, context
// Output: concat( y[:, :, 0] (BATCH,SEQ),  out (BATCH,SEQ,HID) ), fp32.
// ---------------------------------------------------------------------------
extern "C" void kernel_launch(void* const* d_in, const int* in_sizes, int n_in,
                              void* d_out, int out_size) {
    (void)in_sizes; (void)n_in; (void)out_size;
    const float* x    = (const float*)d_in[0];
    const float* h0   = (const float*)d_in[1];
    const float* nois = (const float*)d_in[2];
    const float* Wih  = (const float*)d_in[3];
    const float* Whh  = (const float*)d_in[4];
    const float* Whb  = (const float*)d_in[5];
    const float* bh   = (const float*)d_in[6];
    const float* W    = (const float*)d_in[7];
    const float* bb   = (const float*)d_in[8];
    const void*  ctx  = d_in[9];

    float* y  = (float*)d_out;
    float* ho = y + (size_t)BATCH * SEQ;

    const int smem_bytes = KSM * HID * (int)sizeof(u64)   // 80 KB W
                         + 2 * HID * (int)sizeof(float)   // h double buffer
                         + 16 * (int)sizeof(float);       // warp partials
    cudaFuncSetAttribute(rnn_kernel, cudaFuncAttributeMaxDynamicSharedMemorySize,
                         smem_bytes);

    prep_kernel<<<128, 256>>>(Whh, Whb, ctx);
    rnn_kernel<<<BATCH, HID, smem_bytes>>>(x, h0, nois, Wih, bh, W, bb, y, ho);
}

// round 6
// speedup vs baseline: 1.6676x; 1.6676x over previous
#include <cuda_runtime.h>
#include <cstdint>
#include <cstddef>

#define SEQ   2048
#define BATCH 128
#define HID   256
#define KP    128          // f32-pairs per W row (256 cols / 2)
#define KREG  88           // pairs held in registers per thread (176 cols) — 250 regs, no spill (R1-measured)
#define KSM   (KP - KREG)  // 40 pairs (80 cols) served from shared memory

typedef unsigned long long u64;

// W_eff packed as f32x2 pairs: pair k of row i at g_Wp[k*HID + i]
__device__ u64 g_Wp[KP * HID];

__device__ __forceinline__ u64 ffma2(u64 a, u64 b, u64 c) {
    u64 d;
    asm("fma.rn.f32x2 %0, %1, %2, %3;" : "=l"(d) : "l"(a), "l"(b), "l"(c));
    return d;
}
__device__ __forceinline__ u64 add2(u64 a, u64 b) {
    u64 d;
    asm("add.rn.f32x2 %0, %1, %2;" : "=l"(d) : "l"(a), "l"(b));
    return d;
}
__device__ __forceinline__ float lo32(u64 v) { return __uint_as_float((unsigned)(v & 0xffffffffu)); }
__device__ __forceinline__ float hi32(u64 v) { return __uint_as_float((unsigned)(v >> 32)); }
__device__ __forceinline__ float fast_tanh(float x) {
    float r;
    asm("tanh.approx.f32 %0, %1;" : "=f"(r) : "f"(x));
    return r;
}

// ---------------------------------------------------------------------------
// Prep: W_eff = W_hh + context * W_hh_bias, packed into pair-major layout.
// ---------------------------------------------------------------------------
__global__ void prep_kernel(const float* __restrict__ Whh,
                            const float* __restrict__ Whb,
                            const void*  __restrict__ ctxp) {
    int idx = blockIdx.x * blockDim.x + threadIdx.x;   // 32768 threads
    int k = idx >> 8;
    int i = idx & 255;
    int iv = *(const int*)ctxp;
    float ctx = (iv > -1000000 && iv < 1000000) ? (float)iv : *(const float*)ctxp;
    float w0 = fmaf(ctx, Whb[i * HID + 2 * k],     Whh[i * HID + 2 * k]);
    float w1 = fmaf(ctx, Whb[i * HID + 2 * k + 1], Whh[i * HID + 2 * k + 1]);
    g_Wp[k * HID + i] = (u64)__float_as_uint(w0) | ((u64)__float_as_uint(w1) << 32);
}

// ---------------------------------------------------------------------------
// Persistent recurrence: one CTA per batch element, 256 threads (thread i owns
// hidden unit i). 176 W columns in registers, 80 from smem. One barrier/step.
// No output head inside the loop — head_kernel handles it afterwards.
// ---------------------------------------------------------------------------
__global__ void __launch_bounds__(HID, 1) rnn_kernel(
    const float* __restrict__ x,     const float* __restrict__ h0,
    const float* __restrict__ noise, const float* __restrict__ W_ih,
    const float* __restrict__ b_h,   float* __restrict__ h_out)
{
    extern __shared__ u64 sm[];
    u64*   Wsm = sm;                               // KSM*HID u64 = 80 KB
    float* hb  = (float*)(sm + KSM * HID);         // 2 * HID (double-buffered h)

    const int b = blockIdx.x;
    const int i = threadIdx.x;

    // Stage the smem-resident W pairs (coalesced u64 loads, once).
    for (int idx = i; idx < KSM * HID; idx += HID)
        Wsm[idx] = g_Wp[KREG * HID + idx];

    // Register-resident W pairs (coalesced across threads per k).
    u64 Wreg[KREG];
#pragma unroll
    for (int k = 0; k < KREG; k++) Wreg[k] = g_Wp[k * HID + i];

    const float win = W_ih[i];
    const float bh  = b_h[i];

    hb[i] = h0[b * HID + i];
    __syncthreads();

    const float* np = noise + (size_t)b * HID + i;
    float*       op = h_out + (size_t)b * SEQ * HID + i;
    const float* xp = x + b;

    for (int t = 0; t < SEQ; t++) {
        const int cur = t & 1;

        // Prefetch streamed inputs early; consumed ~700+ cycles later.
        const float nz = __ldg(np + (size_t)t * (BATCH * HID));
        const float xv = __ldg(xp + t * BATCH);

        const ulonglong2* h4 = (const ulonglong2*)(hb + cur * HID);
        u64 a0 = 0, a1 = 0, a2 = 0, a3 = 0;

        // Register part: j in [0, 176)
#pragma unroll
        for (int kk = 0; kk < KREG / 2; kk++) {
            ulonglong2 hh = h4[kk];                  // LDS.128 broadcast
            a0 = ffma2(Wreg[2 * kk],     hh.x, a0);
            a1 = ffma2(Wreg[2 * kk + 1], hh.y, a1);
        }
        // Smem part: j in [176, 256)  (LDS.64: lanes contiguous, conflict-free)
#pragma unroll
        for (int gg = 0; gg < KSM / 2; gg++) {
            ulonglong2 hh = h4[KREG / 2 + gg];
            a2 = ffma2(Wsm[(2 * gg) * HID + i],     hh.x, a2);
            a3 = ffma2(Wsm[(2 * gg + 1) * HID + i], hh.y, a3);
        }

        // Packed reduction tree: 2 packed levels + one lo/hi fold.
        u64 aa = add2(add2(a0, a1), add2(a2, a3));
        float s   = lo32(aa) + hi32(aa);
        float pre = fmaf(xv, win, s) + bh;
        float hn  = fast_tanh(pre) + nz;

        hb[(cur ^ 1) * HID + i] = hn;         // next-step h (other parity slot)
        op[(size_t)t * HID] = hn;             // out[b, t, i] (coalesced)

        __syncthreads();
    }
}

// ---------------------------------------------------------------------------
// Output head: y[b,t] = sigmoid(<out[b,t,:], W[0,:]> + b[0]).
// One warp per (b,t); pure streaming read of 256 MB — memory bound (~50 us).
// ---------------------------------------------------------------------------
__global__ void __launch_bounds__(256) head_kernel(
    const float* __restrict__ ho, const float* __restrict__ W,
    const float* __restrict__ bb, float* __restrict__ y)
{
    const int warp = (blockIdx.x * blockDim.x + threadIdx.x) >> 5;  // (b*SEQ + t)
    const int lane = threadIdx.x & 31;
    if (warp >= BATCH * SEQ) return;

    const float4* p  = (const float4*)(ho + (size_t)warp * HID);
    const float4* w4 = (const float4*)W;   // W[0,:] = first 256 floats

    float4 v0 = p[lane],      v1 = p[lane + 32];
    float4 w0 = w4[lane],     w1 = w4[lane + 32];

    float s = v0.x * w0.x;
    s = fmaf(v0.y, w0.y, s);  s = fmaf(v0.z, w0.z, s);  s = fmaf(v0.w, w0.w, s);
    s = fmaf(v1.x, w1.x, s);  s = fmaf(v1.y, w1.y, s);
    s = fmaf(v1.z, w1.z, s);  s = fmaf(v1.w, w1.w, s);

#pragma unroll
    for (int o = 16; o > 0; o >>= 1) s += __shfl_xor_sync(0xffffffffu, s, o);

    if (lane == 0)
        y[warp] = 1.0f / (1.0f + expf(-(s + bb[0])));
}

// ---------------------------------------------------------------------------
// Launch: inputs in metadata order
//   x, h0, noise, W_ih, W_hh, W_hh_bias, b_h, W, b, context
// Output: concat( y[:, :, 0] (BATCH,SEQ),  out (BATCH,SEQ,HID) ), fp32.
// ---------------------------------------------------------------------------
extern "C" void kernel_launch(void* const* d_in, const int* in_sizes, int n_in,
                              void* d_out, int out_size) {
    (void)in_sizes; (void)n_in; (void)out_size;
    const float* x    = (const float*)d_in[0];
    const float* h0   = (const float*)d_in[1];
    const float* nois = (const float*)d_in[2];
    const float* Wih  = (const float*)d_in[3];
    const float* Whh  = (const float*)d_in[4];
    const float* Whb  = (const float*)d_in[5];
    const float* bh   = (const float*)d_in[6];
    const float* W    = (const float*)d_in[7];
    const float* bb   = (const float*)d_in[8];
    const void*  ctx  = d_in[9];

    float* y  = (float*)d_out;
    float* ho = y + (size_t)BATCH * SEQ;

    const int smem_bytes = KSM * HID * (int)sizeof(u64)   // 80 KB W
                         + 2 * HID * (int)sizeof(float);  // h double buffer
    cudaFuncSetAttribute(rnn_kernel, cudaFuncAttributeMaxDynamicSharedMemorySize,
                         smem_bytes);

    prep_kernel<<<128, 256>>>(Whh, Whb, ctx);
    rnn_kernel<<<BATCH, HID, smem_bytes>>>(x, h0, nois, Wih, bh, ho);

    const int nwarps  = BATCH * SEQ;                 // 262144
    const int nblocks = (nwarps * 32 + 255) / 256;   // 32768
    head_kernel<<<nblocks, 256>>>(ho, W, bb, y);
}

// round 9
// speedup vs baseline: 2.0036x; 1.2014x over previous
#include <cuda_runtime.h>
#include <cstdint>
#include <cstddef>

#define SEQ     2048
#define BATCH   128
#define HID     256
#define KP      128        // f32-pairs per W row
#define THREADS 512        // 2 threads per row: lane pair (even=half0, odd=half1)
#define KPH     64         // pairs per half-row (128 cols)
#define KREG2   40         // pairs in registers per thread (80 regs)
#define KSM2    24         // pairs from smem per thread
#define HBYTES  1056       // bytes per h parity buffer: 512 + 16 pad + 512 (+16 slack)

typedef unsigned long long u64;

// W_eff packed as f32x2 pairs: pair k of row i at g_Wp[k*HID + i]
__device__ u64 g_Wp[KP * HID];

__device__ __forceinline__ u64 ffma2(u64 a, u64 b, u64 c) {
    u64 d;
    asm("fma.rn.f32x2 %0, %1, %2, %3;" : "=l"(d) : "l"(a), "l"(b), "l"(c));
    return d;
}
__device__ __forceinline__ u64 add2(u64 a, u64 b) {
    u64 d;
    asm("add.rn.f32x2 %0, %1, %2;" : "=l"(d) : "l"(a), "l"(b));
    return d;
}
__device__ __forceinline__ float lo32(u64 v) { return __uint_as_float((unsigned)(v & 0xffffffffu)); }
__device__ __forceinline__ float hi32(u64 v) { return __uint_as_float((unsigned)(v >> 32)); }
__device__ __forceinline__ float fast_tanh(float x) {
    float r;
    asm("tanh.approx.f32 %0, %1;" : "=f"(r) : "f"(x));
    return r;
}

// ---------------------------------------------------------------------------
// Prep: W_eff = W_hh + context * W_hh_bias, packed into pair-major layout.
// ---------------------------------------------------------------------------
__global__ void prep_kernel(const float* __restrict__ Whh,
                            const float* __restrict__ Whb,
                            const void*  __restrict__ ctxp) {
    int idx = blockIdx.x * blockDim.x + threadIdx.x;   // 32768 threads
    int k = idx >> 8;
    int i = idx & 255;
    int iv = *(const int*)ctxp;
    float ctx = (iv > -1000000 && iv < 1000000) ? (float)iv : *(const float*)ctxp;
    float w0 = fmaf(ctx, Whb[i * HID + 2 * k],     Whh[i * HID + 2 * k]);
    float w1 = fmaf(ctx, Whb[i * HID + 2 * k + 1], Whh[i * HID + 2 * k + 1]);
    g_Wp[k * HID + i] = (u64)__float_as_uint(w0) | ((u64)__float_as_uint(w1) << 32);
}

// ---------------------------------------------------------------------------
// Persistent recurrence: one CTA per batch element, 512 threads.
// Thread tid: row r = tid>>1, half = tid&1 owns 64 of the row's 128 W-pairs
// (40 in registers, 24 in smem). Halves combine via shfl_xor(1) — one
// __syncthreads per step. h stored with a 16B pad between halves so paired
// even/odd broadcasts land in disjoint bank groups (1 wavefront).
// ---------------------------------------------------------------------------
__global__ void __launch_bounds__(THREADS, 1) rnn_kernel(
    const float* __restrict__ x,     const float* __restrict__ h0,
    const float* __restrict__ noise, const float* __restrict__ W_ih,
    const float* __restrict__ b_h,   float* __restrict__ h_out)
{
    extern __shared__ char smraw[];
    u64*  Wsm   = (u64*)smraw;                         // KSM2*THREADS u64 = 96 KB
    char* hbase = smraw + (size_t)KSM2 * THREADS * 8;  // 2 * HBYTES

    const int b    = blockIdx.x;
    const int tid  = threadIdx.x;
    const int r    = tid >> 1;       // row 0..255
    const int half = tid & 1;        // j-half 0/1
    const int hoff = half * 528;     // byte offset of this half's h region

    // Stage smem-resident W pairs (this thread's pairs 40..63 of its half).
    for (int p = 0; p < KSM2; p++)
        Wsm[p * THREADS + tid] = g_Wp[(half * KPH + KREG2 + p) * HID + r];

    // Register-resident W pairs (this thread's pairs 0..39 of its half).
    u64 Wreg[KREG2];
#pragma unroll
    for (int q = 0; q < KREG2; q++)
        Wreg[q] = g_Wp[(half * KPH + q) * HID + r];

    const float win  = W_ih[r];
    const float bh   = b_h[r];
    // h slot for row r: halves of the h vector are padded apart by 16B.
    const int   slot = (r < 128) ? 4 * r : 528 + 4 * (r - 128);

    if (half == 0) *(float*)(hbase + slot) = h0[b * HID + r];
    __syncthreads();

    const float* np = noise + (size_t)b * HID + r;
    float*       op = h_out + (size_t)b * SEQ * HID + r;
    const float* xp = x + b;

    for (int t = 0; t < SEQ; t++) {
        const char* hc  = hbase + (t & 1) * HBYTES + hoff;          // read side
        char*       hnb = hbase + ((t & 1) ^ 1) * HBYTES;           // write side

        // Prefetch streamed inputs early (consumed ~500+ cycles later).
        float nz = 0.0f;
        if (half == 0) nz = __ldg(np + (size_t)t * (BATCH * HID));
        const float xv = __ldg(xp + t * BATCH);

        u64 a0 = 0, a1 = 0, a2 = 0, a3 = 0;

        // Register part: chunks 0..19 (pairs 0..39 of this half).
#pragma unroll
        for (int kk = 0; kk < KREG2 / 2; kk++) {
            ulonglong2 hh = *(const ulonglong2*)(hc + kk * 16);  // paired broadcast
            a0 = ffma2(Wreg[2 * kk],     hh.x, a0);
            a1 = ffma2(Wreg[2 * kk + 1], hh.y, a1);
        }
        // Smem part: chunks 20..31 (pairs 40..63 of this half).
#pragma unroll
        for (int kk = KREG2 / 2; kk < KPH / 2; kk++) {
            ulonglong2 hh = *(const ulonglong2*)(hc + kk * 16);
            const int p = 2 * kk - KREG2;
            a2 = ffma2(Wsm[p * THREADS + tid],       hh.x, a2);
            a3 = ffma2(Wsm[(p + 1) * THREADS + tid], hh.y, a3);
        }

        // Fold 4 packed accumulators, then combine halves warp-locally.
        u64 aa = add2(add2(a0, a1), add2(a2, a3));
        float s = lo32(aa) + hi32(aa);
        s += __shfl_xor_sync(0xffffffffu, s, 1);

        if (half == 0) {
            float pre = fmaf(xv, win, s) + bh;
            float hv  = fast_tanh(pre) + nz;
            *(float*)(hnb + slot) = hv;      // publish next h
            op[(size_t)t * HID]   = hv;      // out[b, t, r] (streaming)
        }
        __syncthreads();
    }
}

// ---------------------------------------------------------------------------
// Output head: y[b,t] = sigmoid(<out[b,t,:], W[0,:]> + b[0]).
// One warp per (b,t); streaming read of 256 MB — memory bound (~50 us).
// ---------------------------------------------------------------------------
__global__ void __launch_bounds__(256) head_kernel(
    const float* __restrict__ ho, const float* __restrict__ W,
    const float* __restrict__ bb, float* __restrict__ y)
{
    const int warp = (blockIdx.x * blockDim.x + threadIdx.x) >> 5;  // (b*SEQ + t)
    const int lane = threadIdx.x & 31;
    if (warp >= BATCH * SEQ) return;

    const float4* p  = (const float4*)(ho + (size_t)warp * HID);
    const float4* w4 = (const float4*)W;   // W[0,:] = first 256 floats

    float4 v0 = p[lane],      v1 = p[lane + 32];
    float4 w0 = w4[lane],     w1 = w4[lane + 32];

    float s = v0.x * w0.x;
    s = fmaf(v0.y, w0.y, s);  s = fmaf(v0.z, w0.z, s);  s = fmaf(v0.w, w0.w, s);
    s = fmaf(v1.x, w1.x, s);  s = fmaf(v1.y, w1.y, s);
    s = fmaf(v1.z, w1.z, s);  s = fmaf(v1.w, w1.w, s);

#pragma unroll
    for (int o = 16; o > 0; o >>= 1) s += __shfl_xor_sync(0xffffffffu, s, o);

    if (lane == 0)
        y[warp] = 1.0f / (1.0f + expf(-(s + bb[0])));
}

// ---------------------------------------------------------------------------
// Launch: inputs in metadata order
//   x, h0, noise, W_ih, W_hh, W_hh_bias, b_h, W, b, context
// Output: concat( y[:, :, 0] (BATCH,SEQ),  out (BATCH,SEQ,HID) ), fp32.
// ---------------------------------------------------------------------------
extern "C" void kernel_launch(void* const* d_in, const int* in_sizes, int n_in,
                              void* d_out, int out_size) {
    (void)in_sizes; (void)n_in; (void)out_size;
    const float* x    = (const float*)d_in[0];
    const float* h0   = (const float*)d_in[1];
    const float* nois = (const float*)d_in[2];
    const float* Wih  = (const float*)d_in[3];
    const float* Whh  = (const float*)d_in[4];
    const float* Whb  = (const float*)d_in[5];
    const float* bh   = (const float*)d_in[6];
    const float* W    = (const float*)d_in[7];
    const float* bb   = (const float*)d_in[8];
    const void*  ctx  = d_in[9];

    float* y  = (float*)d_out;
    float* ho = y + (size_t)BATCH * SEQ;

    const int smem_bytes = KSM2 * THREADS * (int)sizeof(u64)  // 96 KB W
                         + 2 * HBYTES;                        // padded h buffers
    cudaFuncSetAttribute(rnn_kernel, cudaFuncAttributeMaxDynamicSharedMemorySize,
                         smem_bytes);

    prep_kernel<<<128, 256>>>(Whh, Whb, ctx);
    rnn_kernel<<<BATCH, THREADS, smem_bytes>>>(x, h0, nois, Wih, bh, ho);

    const int nwarps  = BATCH * SEQ;                 // 262144
    const int nblocks = (nwarps * 32 + 255) / 256;   // 32768
    head_kernel<<<nblocks, 256>>>(ho, W, bb, y);
}